// round 16
// baseline (speedup 1.0000x reference)
#include <cuda_runtime.h>
#include <cuda_fp16.h>
#include <cstdint>
#include <cstddef>

// ---------------------------------------------------------------------------
// Grouped SwiGLU FFN:  out = (silu(x@w1) * (x@w3^T)) @ w2^T   per expert
// E=8, T=1024, D=2048, H=4096, fp32 in/out.  sm_103 baseline ISA (mma.sync).
// This round: prep (x/w3 convert + w1 transpose) fused INTO the ffn1 launch
// with per-expert spin counters, so prep overlaps ffn1's DRAM-idle mainloop.
// Block order (1D grid, expert-major): [64 prep][256 ffn1] per expert.
// w2 fp32->fp16 conversion stays in ffn1's 2 dedicated converter warps.
// ---------------------------------------------------------------------------
#define NE 8
#define NT 1024
#define ND 2048
#define NH 4096

static constexpr int BM = 128, BK = 64, STAGES = 4;
static constexpr int CONSUMERS  = 256;               // 8 warps, 2x4
static constexpr int PRODUCERS  = 64;                // 2 warps
static constexpr int CONVERTERS = 64;                // 2 warps (ffn1 only)
static constexpr int THREADS1   = CONSUMERS + PRODUCERS + CONVERTERS;  // 384
static constexpr int THREADS2   = CONSUMERS + PRODUCERS;               // 320
static constexpr int PREP_BLKS  = 64;                // prep blocks per expert
static constexpr int FFN1_BLKS  = 256;               // ffn1 blocks per expert
static constexpr int BLKS_PER_E = PREP_BLKS + FFN1_BLKS;  // 320
// padded smem rows: 64 fp16 = 128 B data + 16 B pad = 144 B stride.
static constexpr uint32_t SR    = 144;
static constexpr uint32_t T128  = BM * SR;           // 18432 B per 128-row tile
static constexpr uint32_t STAGE1 = 3 * T128;         // A+B1+B2 = 55296
static constexpr uint32_t SMEM1  = STAGES * STAGE1;  // 221184
static constexpr uint32_t STAGE2 = 2 * T128;         // A+B     = 36864
static constexpr uint32_t SMEM2  = STAGES * STAGE2;  // 147456

// ---------------------------------------------------------------------------
// Scratch (__device__ bss — no runtime allocation)
// ---------------------------------------------------------------------------
__device__ __half g_x16[(size_t)NE * NT * ND];   //  32 MB  x fp16      [E,T,D]
__device__ __half g_w1t[(size_t)NE * NH * ND];   // 128 MB  w1^T fp16   [E,H,D]
__device__ __half g_w3h[(size_t)NE * NH * ND];   // 128 MB  w3 fp16     [E,H,D]
__device__ __half g_w2h[(size_t)NE * ND * NH];   // 128 MB  w2 fp16     [E,D,H]
__device__ __half g_act[(size_t)NE * NT * NH];   //  64 MB  silu(u)*g   [E,T,H]
__device__ unsigned g_cnt[NE];                   // per-expert prep counters

// ---------------------------------------------------------------------------
// PTX helpers (baseline sm_80/sm_90 features only — no 'a' suffix)
// ---------------------------------------------------------------------------
__device__ __forceinline__ uint32_t smem_u32(const void* p) {
    return (uint32_t)__cvta_generic_to_shared(p);
}

__device__ __forceinline__ void cp16(uint32_t dst, const void* src) {
    asm volatile("cp.async.cg.shared.global [%0], [%1], 16;" ::"r"(dst), "l"(src)
                 : "memory");
}
#define CP_COMMIT() asm volatile("cp.async.commit_group;" ::: "memory")

__device__ __forceinline__ void mbar_init(uint32_t a, uint32_t cnt) {
    asm volatile("mbarrier.init.shared.b64 [%0], %1;" ::"r"(a), "r"(cnt) : "memory");
}
__device__ __forceinline__ void mbar_arrive(uint32_t a) {
    asm volatile("{\n\t.reg .b64 s;\n\tmbarrier.arrive.shared.b64 s, [%0];\n\t}"
                 ::"r"(a) : "memory");
}
__device__ __forceinline__ void mbar_wait(uint32_t a, uint32_t phase) {
    asm volatile(
        "{\n\t.reg .pred P;\n\t"
        "LW_%=:\n\t"
        "mbarrier.try_wait.parity.shared.b64 P, [%0], %1;\n\t"
        "@P bra.uni LD_%=;\n\t"
        "bra.uni LW_%=;\n\t"
        "LD_%=:\n\t}"
        ::"r"(a), "r"(phase) : "memory");
}

__device__ __forceinline__ void ldm_x4(uint32_t* r, uint32_t addr) {
    asm volatile("ldmatrix.sync.aligned.m8n8.x4.shared.b16 {%0,%1,%2,%3}, [%4];"
                 : "=r"(r[0]), "=r"(r[1]), "=r"(r[2]), "=r"(r[3])
                 : "r"(addr));
}

__device__ __forceinline__ void mma16816(float* c, const uint32_t* a,
                                         uint32_t b0, uint32_t b1) {
    asm volatile(
        "mma.sync.aligned.m16n8k16.row.col.f32.f16.f16.f32 "
        "{%0,%1,%2,%3}, {%4,%5,%6,%7}, {%8,%9}, {%0,%1,%2,%3};"
        : "+f"(c[0]), "+f"(c[1]), "+f"(c[2]), "+f"(c[3])
        : "r"(a[0]), "r"(a[1]), "r"(a[2]), "r"(a[3]), "r"(b0), "r"(b1));
}

// ---------------------------------------------------------------------------
// counter reset (head of graph — makes every replay deterministic)
// ---------------------------------------------------------------------------
__global__ void k_reset() {
    if (threadIdx.x < NE) g_cnt[threadIdx.x] = 0u;
}

// ---------------------------------------------------------------------------
// Producer building blocks (cp.async only)
// ---------------------------------------------------------------------------
template <int STRIDE, int ITERS>
__device__ __forceinline__ void fill_f16(uint32_t sd, const __half* __restrict__ g,
                                         int p) {
#pragma unroll
    for (int i = 0; i < ITERS; ++i) {
        int id = p + i * 64;
        int r = id >> 3, c = id & 7;
        cp16(sd + (uint32_t)(r * SR + c * 16), g + (size_t)r * STRIDE + c * 8);
    }
}

// barriers in static smem
struct Bars { uint64_t full[STAGES]; uint64_t empty[STAGES]; };

__device__ __forceinline__ void bars_init(Bars* b, int tid) {
    if (tid == 0) {
#pragma unroll
        for (int s = 0; s < STAGES; ++s) {
            mbar_init(smem_u32(&b->full[s]), PRODUCERS);
            mbar_init(smem_u32(&b->empty[s]), CONSUMERS);
        }
    }
    __syncthreads();
}

#define PROD_SIGNAL(k)                                                         \
    CP_COMMIT();                                                               \
    if ((k) >= 2) {                                                            \
        asm volatile("cp.async.wait_group 2;" ::: "memory");                   \
        mbar_arrive(smem_u32(&bars.full[((k) - 2) & (STAGES - 1)]));           \
    }

#define PROD_DRAIN(KIT)                                                        \
    asm volatile("cp.async.wait_group 1;" ::: "memory");                       \
    mbar_arrive(smem_u32(&bars.full[((KIT) - 2) & (STAGES - 1)]));             \
    asm volatile("cp.async.wait_group 0;" ::: "memory");                       \
    mbar_arrive(smem_u32(&bars.full[((KIT) - 1) & (STAGES - 1)]))

// ---------------------------------------------------------------------------
// Per-expert prep work for one of the 64 prep blocks (384 threads):
//   x slice fp32->fp16, w3 slice fp32->fp16, 32 w1 64x64 transpose tiles.
// ---------------------------------------------------------------------------
__device__ void do_prep(int e, int p, const float* __restrict__ x,
                        const float* __restrict__ w1,
                        const float* __restrict__ w3, char* sm) {
    int tid = threadIdx.x;

    // x: 524288 float4 per expert -> 8192 per block
    {
        const float4* src = reinterpret_cast<const float4*>(x) +
                            (size_t)e * 524288 + (size_t)p * 8192;
        uint2* dst = reinterpret_cast<uint2*>(g_x16) +
                     (size_t)e * 524288 + (size_t)p * 8192;
        for (int i = tid; i < 8192; i += THREADS1) {
            float4 v = src[i];
            __half2 h0 = __floats2half2_rn(v.x, v.y);
            __half2 h1 = __floats2half2_rn(v.z, v.w);
            dst[i] = make_uint2(*reinterpret_cast<uint32_t*>(&h0),
                                *reinterpret_cast<uint32_t*>(&h1));
        }
    }

    // w3: 2097152 float4 per expert -> 32768 per block
    {
        const float4* src = reinterpret_cast<const float4*>(w3) +
                            (size_t)e * 2097152 + (size_t)p * 32768;
        uint2* dst = reinterpret_cast<uint2*>(g_w3h) +
                     (size_t)e * 2097152 + (size_t)p * 32768;
        for (int i = tid; i < 32768; i += THREADS1) {
            float4 v = src[i];
            __half2 h0 = __floats2half2_rn(v.x, v.y);
            __half2 h1 = __floats2half2_rn(v.z, v.w);
            dst[i] = make_uint2(*reinterpret_cast<uint32_t*>(&h0),
                                *reinterpret_cast<uint32_t*>(&h1));
        }
    }

    // w1 transpose: 2048 64x64 tiles per expert -> 32 per block (256 threads)
    float (*t)[65] = reinterpret_cast<float (*)[65]>(sm);
#pragma unroll 1
    for (int tt = 0; tt < 32; ++tt) {
        int tile = p * 32 + tt;
        int h0 = (tile & 63) * 64;       // 64 h-tiles
        int d0 = (tile >> 6) * 64;       // 32 d-tiles
        __syncthreads();
        if (tid < 256) {
            const float* src = w1 + ((size_t)e * ND + d0) * NH + h0;
#pragma unroll
            for (int i = 0; i < 4; ++i) {
                int u = tid + i * 256;
                int r = u >> 4, c4 = u & 15;
                float4 v = *reinterpret_cast<const float4*>(
                    src + (size_t)r * NH + c4 * 4);
                t[r][c4 * 4 + 0] = v.x; t[r][c4 * 4 + 1] = v.y;
                t[r][c4 * 4 + 2] = v.z; t[r][c4 * 4 + 3] = v.w;
            }
        }
        __syncthreads();
        if (tid < 256) {
            __half* dst = g_w1t + ((size_t)e * NH + h0) * ND + d0;
#pragma unroll
            for (int i = 0; i < 2; ++i) {
                int u = tid + i * 256;
                int hr = u >> 3, dc = (u & 7) * 8;
                __half2 h2[4];
#pragma unroll
                for (int j = 0; j < 4; ++j)
                    h2[j] = __floats2half2_rn(t[dc + 2 * j][hr],
                                              t[dc + 2 * j + 1][hr]);
                *reinterpret_cast<uint4*>(dst + (size_t)hr * ND + dc) =
                    *reinterpret_cast<uint4*>(h2);
            }
        }
    }
}

// ---------------------------------------------------------------------------
// Fused prep + phase 1:  act = silu(x@w1t^T) * (x@w3^T)  -> g_act fp16
// 1D grid of NE*320 blocks: per expert, blocks [0,64) = prep, [64,320) = ffn1
// (8 consumer warps 2x4 + 2 producer warps + 2 w2-converter warps).
// ---------------------------------------------------------------------------
__global__ void __launch_bounds__(THREADS1, 1)
k_prep_ffn1(const float* __restrict__ x,  const float* __restrict__ w1,
            const float* __restrict__ w3, const float* __restrict__ w2) {
    extern __shared__ __align__(128) char sm[];
    __shared__ Bars bars;
    uint32_t base = smem_u32(sm);
    int tid = threadIdx.x, lane = tid & 31, wid = tid >> 5;
    int bid = blockIdx.x;
    int e = bid / BLKS_PER_E;
    int local = bid % BLKS_PER_E;
    constexpr int KIT = ND / BK;  // 32

    if (local < PREP_BLKS) {                          // ---- prep blocks
        do_prep(e, local, x, w1, w3, sm);
        __syncthreads();
        __threadfence();
        if (tid == 0) atomicAdd(&g_cnt[e], 1u);
        return;
    }

    int idx = local - PREP_BLKS;                      // 0..255
    int bx = idx & 7;                                 // M tile (8)
    int by = idx >> 3;                                // N tile (32)

    bars_init(&bars, tid);

    if (tid >= CONSUMERS + PRODUCERS) {               // ---- converter warps
        // no dependency on prep: convert this block's w2 slice immediately.
        // NE*256 blocks x 64 threads x 128 float4 = E*D*H/4 = 16,777,216.
        int p = tid - (CONSUMERS + PRODUCERS);
        size_t cta = (size_t)e * FFN1_BLKS + idx;
        const float4* src = reinterpret_cast<const float4*>(w2) + cta * 8192;
        uint2* dst = reinterpret_cast<uint2*>(g_w2h) + cta * 8192;
#pragma unroll 1
        for (int i = 0; i < 128; i += 8) {
            float4 v[8];
#pragma unroll
            for (int j = 0; j < 8; ++j) v[j] = src[p + (i + j) * 64];
#pragma unroll
            for (int j = 0; j < 8; ++j) {
                __half2 h0 = __floats2half2_rn(v[j].x, v[j].y);
                __half2 h1 = __floats2half2_rn(v[j].z, v[j].w);
                dst[p + (i + j) * 64] =
                    make_uint2(*reinterpret_cast<uint32_t*>(&h0),
                               *reinterpret_cast<uint32_t*>(&h1));
            }
        }
        return;
    }

    // ---- spin until this expert's prep is complete (leader-poll + fence)
    if (tid == 0) {
        while (atomicAdd(&g_cnt[e], 0u) < (unsigned)PREP_BLKS) __nanosleep(128);
        __threadfence();
    }
    __syncthreads();

    const __half* A  = g_x16 + ((size_t)e * NT + bx * BM) * ND;
    const __half* B1 = g_w1t + ((size_t)e * NH + by * 128) * ND;
    const __half* B2 = g_w3h + ((size_t)e * NH + by * 128) * ND;

    if (tid >= CONSUMERS) {                           // ---- producer warps
        int p = tid - CONSUMERS;
#pragma unroll 1
        for (int k = 0; k < KIT; ++k) {
            int s = k & (STAGES - 1);
            if (k >= STAGES)
                mbar_wait(smem_u32(&bars.empty[s]), ((k >> 2) - 1) & 1);
            uint32_t s0 = base + (uint32_t)s * STAGE1;
            int ko = k * BK;
            fill_f16<ND, 16>(s0,            A  + ko, p);
            fill_f16<ND, 16>(s0 + T128,     B1 + ko, p);
            fill_f16<ND, 16>(s0 + 2 * T128, B2 + ko, p);
            PROD_SIGNAL(k);
        }
        PROD_DRAIN(KIT);
        return;
    }

    // ---- consumer warps: wm in {0,1} (64 M-rows), wn in {0..3} (32 N-cols)
    int wm = wid >> 2, wn = wid & 3;
    float c[2][4][4][4];                              // [B][mi][ni][frag]
#pragma unroll
    for (int b = 0; b < 2; ++b)
#pragma unroll
        for (int mi = 0; mi < 4; ++mi)
#pragma unroll
            for (int ni = 0; ni < 4; ++ni)
#pragma unroll
                for (int q = 0; q < 4; ++q) c[b][mi][ni][q] = 0.f;

    uint32_t a_off = (uint32_t)((wm * 64 + (lane & 15)) * SR + (lane >> 4) * 16);
    uint32_t b_off = (uint32_t)((wn * 32 + ((lane >> 4) << 3) + (lane & 7)) * SR +
                                ((lane >> 3) & 1) * 16);

#pragma unroll 1
    for (int k = 0; k < KIT; ++k) {
        int s = k & (STAGES - 1);
        mbar_wait(smem_u32(&bars.full[s]), (k >> 2) & 1);
        uint32_t s0 = base + (uint32_t)s * STAGE1;
#pragma unroll
        for (int ks = 0; ks < 4; ++ks) {              // 4 x K=16 steps
            uint32_t ra[4][4], rb[2][2][4];
#pragma unroll
            for (int mi = 0; mi < 4; ++mi)
                ldm_x4(ra[mi], s0 + a_off + (uint32_t)(mi * 16 * SR + ks * 32));
#pragma unroll
            for (int b = 0; b < 2; ++b)
#pragma unroll
                for (int nj = 0; nj < 2; ++nj)
                    ldm_x4(rb[b][nj], s0 + (uint32_t)((b + 1) * T128) + b_off +
                                      (uint32_t)(nj * 16 * SR + ks * 32));
#pragma unroll
            for (int b = 0; b < 2; ++b)
#pragma unroll
                for (int mi = 0; mi < 4; ++mi)
#pragma unroll
                    for (int ni = 0; ni < 4; ++ni)
                        mma16816(c[b][mi][ni], ra[mi],
                                 rb[b][ni >> 1][(ni & 1) * 2],
                                 rb[b][ni >> 1][(ni & 1) * 2 + 1]);
        }
        mbar_arrive(smem_u32(&bars.empty[s]));
    }

    // fused SiLU-gate epilogue -> g_act fp16
    int t0 = bx * BM + wm * 64 + (lane >> 2);
    int h0 = by * 128 + wn * 32 + (lane & 3) * 2;
    __half* dst = g_act + (size_t)e * NT * NH;
#pragma unroll
    for (int mi = 0; mi < 4; ++mi)
#pragma unroll
        for (int ni = 0; ni < 4; ++ni) {
            int r = t0 + mi * 16, col = h0 + ni * 8;
            float* u = c[0][mi][ni];
            float* g = c[1][mi][ni];
            float a0 = g[0] * u[0] / (1.f + __expf(-u[0]));
            float a1 = g[1] * u[1] / (1.f + __expf(-u[1]));
            float a2 = g[2] * u[2] / (1.f + __expf(-u[2]));
            float a3 = g[3] * u[3] / (1.f + __expf(-u[3]));
            *reinterpret_cast<__half2*>(dst + (size_t)r * NH + col) =
                __floats2half2_rn(a0, a1);
            *reinterpret_cast<__half2*>(dst + (size_t)(r + 8) * NH + col) =
                __floats2half2_rn(a2, a3);
        }
}

// ---------------------------------------------------------------------------
// Phase 2: out = act @ w2^T   (K=4096, N=2048, fp32 out)
// BN=128 (grid 1024).  8 consumer warps (2x4): warp tile 64 x 32.
// ---------------------------------------------------------------------------
__global__ void __launch_bounds__(THREADS2, 1) k_ffn2(float* __restrict__ out) {
    extern __shared__ __align__(128) char sm[];
    __shared__ Bars bars;
    uint32_t base = smem_u32(sm);
    int tid = threadIdx.x, lane = tid & 31, wid = tid >> 5;
    int e = blockIdx.z;
    constexpr int KIT = NH / BK;  // 64

    const __half* A = g_act + ((size_t)e * NT + blockIdx.y * BM) * NH;
    const __half* B = g_w2h + ((size_t)e * ND + blockIdx.x * 128) * NH;

    bars_init(&bars, tid);

    if (tid >= CONSUMERS) {                           // ---- producer warps
        int p = tid - CONSUMERS;
#pragma unroll 1
        for (int k = 0; k < KIT; ++k) {
            int s = k & (STAGES - 1);
            if (k >= STAGES)
                mbar_wait(smem_u32(&bars.empty[s]), ((k >> 2) - 1) & 1);
            uint32_t s0 = base + (uint32_t)s * STAGE2;
            int ko = k * BK;
            fill_f16<NH, 16>(s0,        A + ko, p);
            fill_f16<NH, 16>(s0 + T128, B + ko, p);
            PROD_SIGNAL(k);
        }
        PROD_DRAIN(KIT);
        return;
    }

    // ---- consumer warps: wm in {0,1}, wn in {0..3} (32-col slices)
    int wm = wid >> 2, wn = wid & 3;
    float c[4][4][4];
#pragma unroll
    for (int mi = 0; mi < 4; ++mi)
#pragma unroll
        for (int ni = 0; ni < 4; ++ni)
#pragma unroll
            for (int q = 0; q < 4; ++q) c[mi][ni][q] = 0.f;

    uint32_t a_off = (uint32_t)((wm * 64 + (lane & 15)) * SR + (lane >> 4) * 16);
    uint32_t b_off = T128 +
        (uint32_t)((wn * 32 + ((lane >> 4) << 3) + (lane & 7)) * SR +
                   ((lane >> 3) & 1) * 16);

#pragma unroll 1
    for (int k = 0; k < KIT; ++k) {
        int s = k & (STAGES - 1);
        mbar_wait(smem_u32(&bars.full[s]), (k >> 2) & 1);
        uint32_t s0 = base + (uint32_t)s * STAGE2;
#pragma unroll
        for (int ks = 0; ks < 4; ++ks) {
            uint32_t ra[4][4], rb[2][4];
#pragma unroll
            for (int mi = 0; mi < 4; ++mi)
                ldm_x4(ra[mi], s0 + a_off + (uint32_t)(mi * 16 * SR + ks * 32));
#pragma unroll
            for (int nj = 0; nj < 2; ++nj)
                ldm_x4(rb[nj], s0 + b_off + (uint32_t)(nj * 16 * SR + ks * 32));
#pragma unroll
            for (int mi = 0; mi < 4; ++mi)
#pragma unroll
                for (int ni = 0; ni < 4; ++ni)
                    mma16816(c[mi][ni], ra[mi],
                             rb[ni >> 1][(ni & 1) * 2], rb[ni >> 1][(ni & 1) * 2 + 1]);
        }
        mbar_arrive(smem_u32(&bars.empty[s]));
    }

    int t0 = blockIdx.y * BM + wm * 64 + (lane >> 2);
    int n0 = blockIdx.x * 128 + wn * 32 + (lane & 3) * 2;
    float* C = out + (size_t)e * NT * ND;
#pragma unroll
    for (int mi = 0; mi < 4; ++mi)
#pragma unroll
        for (int ni = 0; ni < 4; ++ni) {
            int r = t0 + mi * 16, col = n0 + ni * 8;
            *reinterpret_cast<float2*>(C + (size_t)r * ND + col) =
                make_float2(c[mi][ni][0], c[mi][ni][1]);
            *reinterpret_cast<float2*>(C + (size_t)(r + 8) * ND + col) =
                make_float2(c[mi][ni][2], c[mi][ni][3]);
        }
}

// ---------------------------------------------------------------------------
// Launch (graph-capturable: kernel launches only)
// ---------------------------------------------------------------------------
extern "C" void kernel_launch(void* const* d_in, const int* in_sizes, int n_in,
                              void* d_out, int out_size) {
    const float* x  = (const float*)d_in[0];
    const float* w1 = (const float*)d_in[1];
    const float* w2 = (const float*)d_in[2];
    const float* w3 = (const float*)d_in[3];
    float* out = (float*)d_out;

    cudaFuncSetAttribute(k_prep_ffn1,
                         cudaFuncAttributeMaxDynamicSharedMemorySize, SMEM1);
    cudaFuncSetAttribute(k_ffn2,
                         cudaFuncAttributeMaxDynamicSharedMemorySize, SMEM2);

    // reset per-expert prep counters (graph-replay safe)
    k_reset<<<1, 32>>>();

    // fused prep + up/gate/silu; blocks expert-major: [64 prep][256 ffn1] x 8
    k_prep_ffn1<<<NE * BLKS_PER_E, THREADS1, SMEM1>>>(x, w1, w3, w2);

    // down-proj (K=H=4096, N=D=2048 in BN=128 tiles, fp32 out)
    k_ffn2<<<dim3(ND / 128, NT / BM, NE), THREADS2, SMEM2>>>(out);
}

// round 17
// speedup vs baseline: 1.4515x; 1.4515x over previous
#include <cuda_runtime.h>
#include <cuda_fp16.h>
#include <cstdint>
#include <cstddef>

// ---------------------------------------------------------------------------
// Grouped SwiGLU FFN:  out = (silu(x@w1) * (x@w3^T)) @ w2^T   per expert
// E=8, T=1024, D=2048, H=4096, fp32 in/out.  sm_103 baseline ISA (mma.sync),
// warp-specialized producer/consumer pipeline (R15 configuration — the R16
// fused prep+ffn1 spin-dependency variant cost +490us and is abandoned).
// Prep is ONE kernel (x convert / w3 convert / w1 transpose by block range).
// w2 fp32->fp16 conversion runs in ffn1's 2 dedicated converter warps,
// concurrent with the whole mainloop.
// ---------------------------------------------------------------------------
#define NE 8
#define NT 1024
#define ND 2048
#define NH 4096

static constexpr int BM = 128, BK = 64, STAGES = 4;
static constexpr int CONSUMERS  = 256;               // 8 warps, 2x4
static constexpr int PRODUCERS  = 64;                // 2 warps
static constexpr int CONVERTERS = 64;                // 2 warps (ffn1 only)
static constexpr int THREADS1   = CONSUMERS + PRODUCERS + CONVERTERS;  // 384
static constexpr int THREADS2   = CONSUMERS + PRODUCERS;               // 320
// padded smem rows: 64 fp16 = 128 B data + 16 B pad = 144 B stride.
static constexpr uint32_t SR    = 144;
static constexpr uint32_t T128  = BM * SR;           // 18432 B per 128-row tile
static constexpr uint32_t STAGE1 = 3 * T128;         // A+B1+B2 = 55296
static constexpr uint32_t SMEM1  = STAGES * STAGE1;  // 221184
static constexpr uint32_t STAGE2 = 2 * T128;         // A+B     = 36864
static constexpr uint32_t SMEM2  = STAGES * STAGE2;  // 147456

// prep block ranges (single launch)
static constexpr int PREP_X_BLKS  = 16384;   // E*T*D/4 float4 / 256 thr
static constexpr int PREP_W3_BLKS = 65536;   // E*D*H/4 float4 / 256 thr
static constexpr int PREP_W1_BLKS = 16384;   // E * (2048 64x64 tiles)
static constexpr int PREP_BLKS_TOT = PREP_X_BLKS + PREP_W3_BLKS + PREP_W1_BLKS;

// ---------------------------------------------------------------------------
// Scratch (__device__ bss — no runtime allocation)
// ---------------------------------------------------------------------------
__device__ __half g_x16[(size_t)NE * NT * ND];   //  32 MB  x fp16      [E,T,D]
__device__ __half g_w1t[(size_t)NE * NH * ND];   // 128 MB  w1^T fp16   [E,H,D]
__device__ __half g_w3h[(size_t)NE * NH * ND];   // 128 MB  w3 fp16     [E,H,D]
__device__ __half g_w2h[(size_t)NE * ND * NH];   // 128 MB  w2 fp16     [E,D,H]
__device__ __half g_act[(size_t)NE * NT * NH];   //  64 MB  silu(u)*g   [E,T,H]

// ---------------------------------------------------------------------------
// PTX helpers (baseline sm_80/sm_90 features only — no 'a' suffix)
// ---------------------------------------------------------------------------
__device__ __forceinline__ uint32_t smem_u32(const void* p) {
    return (uint32_t)__cvta_generic_to_shared(p);
}

__device__ __forceinline__ void cp16(uint32_t dst, const void* src) {
    asm volatile("cp.async.cg.shared.global [%0], [%1], 16;" ::"r"(dst), "l"(src)
                 : "memory");
}
#define CP_COMMIT() asm volatile("cp.async.commit_group;" ::: "memory")

__device__ __forceinline__ void mbar_init(uint32_t a, uint32_t cnt) {
    asm volatile("mbarrier.init.shared.b64 [%0], %1;" ::"r"(a), "r"(cnt) : "memory");
}
__device__ __forceinline__ void mbar_arrive(uint32_t a) {
    asm volatile("{\n\t.reg .b64 s;\n\tmbarrier.arrive.shared.b64 s, [%0];\n\t}"
                 ::"r"(a) : "memory");
}
__device__ __forceinline__ void mbar_wait(uint32_t a, uint32_t phase) {
    asm volatile(
        "{\n\t.reg .pred P;\n\t"
        "LW_%=:\n\t"
        "mbarrier.try_wait.parity.shared.b64 P, [%0], %1;\n\t"
        "@P bra.uni LD_%=;\n\t"
        "bra.uni LW_%=;\n\t"
        "LD_%=:\n\t}"
        ::"r"(a), "r"(phase) : "memory");
}

__device__ __forceinline__ void ldm_x4(uint32_t* r, uint32_t addr) {
    asm volatile("ldmatrix.sync.aligned.m8n8.x4.shared.b16 {%0,%1,%2,%3}, [%4];"
                 : "=r"(r[0]), "=r"(r[1]), "=r"(r[2]), "=r"(r[3])
                 : "r"(addr));
}

__device__ __forceinline__ void mma16816(float* c, const uint32_t* a,
                                         uint32_t b0, uint32_t b1) {
    asm volatile(
        "mma.sync.aligned.m16n8k16.row.col.f32.f16.f16.f32 "
        "{%0,%1,%2,%3}, {%4,%5,%6,%7}, {%8,%9}, {%0,%1,%2,%3};"
        : "+f"(c[0]), "+f"(c[1]), "+f"(c[2]), "+f"(c[3])
        : "r"(a[0]), "r"(a[1]), "r"(a[2]), "r"(a[3]), "r"(b0), "r"(b1));
}

// ---------------------------------------------------------------------------
// prep: ONE kernel. Block ranges: [0,16384) x convert; [16384,81920) w3
// convert; [81920,98304) w1 64x64 transpose tiles.
// ---------------------------------------------------------------------------
__global__ void __launch_bounds__(256) k_prep(const float* __restrict__ x,
                                              const float* __restrict__ w3,
                                              const float* __restrict__ w1) {
    __shared__ float t[64][65];
    int bid = blockIdx.x, tid = threadIdx.x;

    if (bid < PREP_X_BLKS) {
        size_t i = (size_t)bid * 256 + tid;
        float4 v = reinterpret_cast<const float4*>(x)[i];
        reinterpret_cast<__half2*>(g_x16)[2 * i]     = __floats2half2_rn(v.x, v.y);
        reinterpret_cast<__half2*>(g_x16)[2 * i + 1] = __floats2half2_rn(v.z, v.w);
        return;
    }
    if (bid < PREP_X_BLKS + PREP_W3_BLKS) {
        size_t i = (size_t)(bid - PREP_X_BLKS) * 256 + tid;
        float4 v = reinterpret_cast<const float4*>(w3)[i];
        reinterpret_cast<__half2*>(g_w3h)[2 * i]     = __floats2half2_rn(v.x, v.y);
        reinterpret_cast<__half2*>(g_w3h)[2 * i + 1] = __floats2half2_rn(v.z, v.w);
        return;
    }

    // w1 transpose: linear tile id -> (e, h-tile, d-tile); 64x64 fp32 -> fp16
    int tile = bid - (PREP_X_BLKS + PREP_W3_BLKS);    // 0..16383
    int e  = tile >> 11;                              // /2048
    int r2 = tile & 2047;
    int h0 = (r2 & 63) * 64;                          // 64 h-tiles
    int d0 = (r2 >> 6) * 64;                          // 32 d-tiles
    const float* src = w1 + ((size_t)e * ND + d0) * NH + h0;
#pragma unroll
    for (int i = 0; i < 4; ++i) {
        int u = tid + i * 256;
        int r = u >> 4, c4 = u & 15;
        float4 v = *reinterpret_cast<const float4*>(src + (size_t)r * NH + c4 * 4);
        t[r][c4 * 4 + 0] = v.x; t[r][c4 * 4 + 1] = v.y;
        t[r][c4 * 4 + 2] = v.z; t[r][c4 * 4 + 3] = v.w;
    }
    __syncthreads();
    __half* dst = g_w1t + ((size_t)e * NH + h0) * ND + d0;
#pragma unroll
    for (int i = 0; i < 2; ++i) {
        int u = tid + i * 256;
        int hr = u >> 3, dc = (u & 7) * 8;
        __half2 h2[4];
#pragma unroll
        for (int j = 0; j < 4; ++j)
            h2[j] = __floats2half2_rn(t[dc + 2 * j][hr], t[dc + 2 * j + 1][hr]);
        *reinterpret_cast<uint4*>(dst + (size_t)hr * ND + dc) =
            *reinterpret_cast<uint4*>(h2);
    }
}

// ---------------------------------------------------------------------------
// Producer building blocks (cp.async only)
// ---------------------------------------------------------------------------
template <int STRIDE, int ITERS>
__device__ __forceinline__ void fill_f16(uint32_t sd, const __half* __restrict__ g,
                                         int p) {
#pragma unroll
    for (int i = 0; i < ITERS; ++i) {
        int id = p + i * 64;
        int r = id >> 3, c = id & 7;
        cp16(sd + (uint32_t)(r * SR + c * 16), g + (size_t)r * STRIDE + c * 8);
    }
}

// barriers in static smem
struct Bars { uint64_t full[STAGES]; uint64_t empty[STAGES]; };

__device__ __forceinline__ void bars_init(Bars* b, int tid) {
    if (tid == 0) {
#pragma unroll
        for (int s = 0; s < STAGES; ++s) {
            mbar_init(smem_u32(&b->full[s]), PRODUCERS);
            mbar_init(smem_u32(&b->empty[s]), CONSUMERS);
        }
    }
    __syncthreads();
}

#define PROD_SIGNAL(k)                                                         \
    CP_COMMIT();                                                               \
    if ((k) >= 2) {                                                            \
        asm volatile("cp.async.wait_group 2;" ::: "memory");                   \
        mbar_arrive(smem_u32(&bars.full[((k) - 2) & (STAGES - 1)]));           \
    }

#define PROD_DRAIN(KIT)                                                        \
    asm volatile("cp.async.wait_group 1;" ::: "memory");                       \
    mbar_arrive(smem_u32(&bars.full[((KIT) - 2) & (STAGES - 1)]));             \
    asm volatile("cp.async.wait_group 0;" ::: "memory");                       \
    mbar_arrive(smem_u32(&bars.full[((KIT) - 1) & (STAGES - 1)]))

// ---------------------------------------------------------------------------
// Phase 1 (fused): u = x@w1t^T, g = x@w3^T, act = silu(u)*g  -> g_act fp16
// 8 consumer warps (2x4) + 2 producer warps + 2 converter warps (w2 fp32->
// fp16 concurrent with the whole mainloop).
// ---------------------------------------------------------------------------
__global__ void __launch_bounds__(THREADS1, 1) k_ffn1(const float* __restrict__ w2) {
    extern __shared__ __align__(128) char sm[];
    __shared__ Bars bars;
    uint32_t base = smem_u32(sm);
    int tid = threadIdx.x, lane = tid & 31, wid = tid >> 5;
    int e = blockIdx.z;
    constexpr int KIT = ND / BK;  // 32

    bars_init(&bars, tid);

    if (tid >= CONSUMERS + PRODUCERS) {               // ---- converter warps
        // 2048 CTAs x 64 threads x 128 float4 covers E*D*H/4 = 16,777,216.
        int p = tid - (CONSUMERS + PRODUCERS);
        size_t cta = (size_t)blockIdx.x +
                     8 * ((size_t)blockIdx.y + 32 * (size_t)blockIdx.z);
        const float4* src = reinterpret_cast<const float4*>(w2) + cta * 8192;
        uint2* dst = reinterpret_cast<uint2*>(g_w2h) + cta * 8192;
#pragma unroll 1
        for (int i = 0; i < 128; i += 8) {
            float4 v[8];
#pragma unroll
            for (int j = 0; j < 8; ++j) v[j] = src[p + (i + j) * 64];
#pragma unroll
            for (int j = 0; j < 8; ++j) {
                __half2 h0 = __floats2half2_rn(v[j].x, v[j].y);
                __half2 h1 = __floats2half2_rn(v[j].z, v[j].w);
                dst[p + (i + j) * 64] =
                    make_uint2(*reinterpret_cast<uint32_t*>(&h0),
                               *reinterpret_cast<uint32_t*>(&h1));
            }
        }
        return;
    }

    const __half* A  = g_x16 + ((size_t)e * NT + blockIdx.x * BM) * ND;
    const __half* B1 = g_w1t + ((size_t)e * NH + blockIdx.y * 128) * ND;
    const __half* B2 = g_w3h + ((size_t)e * NH + blockIdx.y * 128) * ND;

    if (tid >= CONSUMERS) {                           // ---- producer warps
        int p = tid - CONSUMERS;
#pragma unroll 1
        for (int k = 0; k < KIT; ++k) {
            int s = k & (STAGES - 1);
            if (k >= STAGES)
                mbar_wait(smem_u32(&bars.empty[s]), ((k >> 2) - 1) & 1);
            uint32_t s0 = base + (uint32_t)s * STAGE1;
            int ko = k * BK;
            fill_f16<ND, 16>(s0,            A  + ko, p);
            fill_f16<ND, 16>(s0 + T128,     B1 + ko, p);
            fill_f16<ND, 16>(s0 + 2 * T128, B2 + ko, p);
            PROD_SIGNAL(k);
        }
        PROD_DRAIN(KIT);
        return;
    }

    // ---- consumer warps: wm in {0,1} (64 M-rows), wn in {0..3} (32 N-cols)
    int wm = wid >> 2, wn = wid & 3;
    float c[2][4][4][4];                              // [B][mi][ni][frag]
#pragma unroll
    for (int b = 0; b < 2; ++b)
#pragma unroll
        for (int mi = 0; mi < 4; ++mi)
#pragma unroll
            for (int ni = 0; ni < 4; ++ni)
#pragma unroll
                for (int q = 0; q < 4; ++q) c[b][mi][ni][q] = 0.f;

    uint32_t a_off = (uint32_t)((wm * 64 + (lane & 15)) * SR + (lane >> 4) * 16);
    uint32_t b_off = (uint32_t)((wn * 32 + ((lane >> 4) << 3) + (lane & 7)) * SR +
                                ((lane >> 3) & 1) * 16);

#pragma unroll 1
    for (int k = 0; k < KIT; ++k) {
        int s = k & (STAGES - 1);
        mbar_wait(smem_u32(&bars.full[s]), (k >> 2) & 1);
        uint32_t s0 = base + (uint32_t)s * STAGE1;
#pragma unroll
        for (int ks = 0; ks < 4; ++ks) {              // 4 x K=16 steps
            uint32_t ra[4][4], rb[2][2][4];
#pragma unroll
            for (int mi = 0; mi < 4; ++mi)
                ldm_x4(ra[mi], s0 + a_off + (uint32_t)(mi * 16 * SR + ks * 32));
#pragma unroll
            for (int b = 0; b < 2; ++b)
#pragma unroll
                for (int nj = 0; nj < 2; ++nj)
                    ldm_x4(rb[b][nj], s0 + (uint32_t)((b + 1) * T128) + b_off +
                                      (uint32_t)(nj * 16 * SR + ks * 32));
#pragma unroll
            for (int b = 0; b < 2; ++b)
#pragma unroll
                for (int mi = 0; mi < 4; ++mi)
#pragma unroll
                    for (int ni = 0; ni < 4; ++ni)
                        mma16816(c[b][mi][ni], ra[mi],
                                 rb[b][ni >> 1][(ni & 1) * 2],
                                 rb[b][ni >> 1][(ni & 1) * 2 + 1]);
        }
        mbar_arrive(smem_u32(&bars.empty[s]));
    }

    // fused SiLU-gate epilogue -> g_act fp16
    int t0 = blockIdx.x * BM + wm * 64 + (lane >> 2);
    int h0 = blockIdx.y * 128 + wn * 32 + (lane & 3) * 2;
    __half* dst = g_act + (size_t)e * NT * NH;
#pragma unroll
    for (int mi = 0; mi < 4; ++mi)
#pragma unroll
        for (int ni = 0; ni < 4; ++ni) {
            int r = t0 + mi * 16, col = h0 + ni * 8;
            float* u = c[0][mi][ni];
            float* g = c[1][mi][ni];
            float a0 = g[0] * u[0] / (1.f + __expf(-u[0]));
            float a1 = g[1] * u[1] / (1.f + __expf(-u[1]));
            float a2 = g[2] * u[2] / (1.f + __expf(-u[2]));
            float a3 = g[3] * u[3] / (1.f + __expf(-u[3]));
            *reinterpret_cast<__half2*>(dst + (size_t)r * NH + col) =
                __floats2half2_rn(a0, a1);
            *reinterpret_cast<__half2*>(dst + (size_t)(r + 8) * NH + col) =
                __floats2half2_rn(a2, a3);
        }
}

// ---------------------------------------------------------------------------
// Phase 2: out = act @ w2^T   (K=4096, N=2048, fp32 out)
// BN=128 (grid 1024).  8 consumer warps (2x4): warp tile 64 x 32.
// ---------------------------------------------------------------------------
__global__ void __launch_bounds__(THREADS2, 1) k_ffn2(float* __restrict__ out) {
    extern __shared__ __align__(128) char sm[];
    __shared__ Bars bars;
    uint32_t base = smem_u32(sm);
    int tid = threadIdx.x, lane = tid & 31, wid = tid >> 5;
    int e = blockIdx.z;
    constexpr int KIT = NH / BK;  // 64

    const __half* A = g_act + ((size_t)e * NT + blockIdx.y * BM) * NH;
    const __half* B = g_w2h + ((size_t)e * ND + blockIdx.x * 128) * NH;

    bars_init(&bars, tid);

    if (tid >= CONSUMERS) {                           // ---- producer warps
        int p = tid - CONSUMERS;
#pragma unroll 1
        for (int k = 0; k < KIT; ++k) {
            int s = k & (STAGES - 1);
            if (k >= STAGES)
                mbar_wait(smem_u32(&bars.empty[s]), ((k >> 2) - 1) & 1);
            uint32_t s0 = base + (uint32_t)s * STAGE2;
            int ko = k * BK;
            fill_f16<NH, 16>(s0,        A + ko, p);
            fill_f16<NH, 16>(s0 + T128, B + ko, p);
            PROD_SIGNAL(k);
        }
        PROD_DRAIN(KIT);
        return;
    }

    // ---- consumer warps: wm in {0,1}, wn in {0..3} (32-col slices)
    int wm = wid >> 2, wn = wid & 3;
    float c[4][4][4];
#pragma unroll
    for (int mi = 0; mi < 4; ++mi)
#pragma unroll
        for (int ni = 0; ni < 4; ++ni)
#pragma unroll
            for (int q = 0; q < 4; ++q) c[mi][ni][q] = 0.f;

    uint32_t a_off = (uint32_t)((wm * 64 + (lane & 15)) * SR + (lane >> 4) * 16);
    uint32_t b_off = T128 +
        (uint32_t)((wn * 32 + ((lane >> 4) << 3) + (lane & 7)) * SR +
                   ((lane >> 3) & 1) * 16);

#pragma unroll 1
    for (int k = 0; k < KIT; ++k) {
        int s = k & (STAGES - 1);
        mbar_wait(smem_u32(&bars.full[s]), (k >> 2) & 1);
        uint32_t s0 = base + (uint32_t)s * STAGE2;
#pragma unroll
        for (int ks = 0; ks < 4; ++ks) {
            uint32_t ra[4][4], rb[2][4];
#pragma unroll
            for (int mi = 0; mi < 4; ++mi)
                ldm_x4(ra[mi], s0 + a_off + (uint32_t)(mi * 16 * SR + ks * 32));
#pragma unroll
            for (int nj = 0; nj < 2; ++nj)
                ldm_x4(rb[nj], s0 + b_off + (uint32_t)(nj * 16 * SR + ks * 32));
#pragma unroll
            for (int mi = 0; mi < 4; ++mi)
#pragma unroll
                for (int ni = 0; ni < 4; ++ni)
                    mma16816(c[mi][ni], ra[mi],
                             rb[ni >> 1][(ni & 1) * 2], rb[ni >> 1][(ni & 1) * 2 + 1]);
        }
        mbar_arrive(smem_u32(&bars.empty[s]));
    }

    int t0 = blockIdx.y * BM + wm * 64 + (lane >> 2);
    int n0 = blockIdx.x * 128 + wn * 32 + (lane & 3) * 2;
    float* C = out + (size_t)e * NT * ND;
#pragma unroll
    for (int mi = 0; mi < 4; ++mi)
#pragma unroll
        for (int ni = 0; ni < 4; ++ni) {
            int r = t0 + mi * 16, col = n0 + ni * 8;
            *reinterpret_cast<float2*>(C + (size_t)r * ND + col) =
                make_float2(c[mi][ni][0], c[mi][ni][1]);
            *reinterpret_cast<float2*>(C + (size_t)(r + 8) * ND + col) =
                make_float2(c[mi][ni][2], c[mi][ni][3]);
        }
}

// ---------------------------------------------------------------------------
// Launch (graph-capturable: kernel launches only)
// ---------------------------------------------------------------------------
extern "C" void kernel_launch(void* const* d_in, const int* in_sizes, int n_in,
                              void* d_out, int out_size) {
    const float* x  = (const float*)d_in[0];
    const float* w1 = (const float*)d_in[1];
    const float* w2 = (const float*)d_in[2];
    const float* w3 = (const float*)d_in[3];
    float* out = (float*)d_out;

    cudaFuncSetAttribute(k_ffn1, cudaFuncAttributeMaxDynamicSharedMemorySize, SMEM1);
    cudaFuncSetAttribute(k_ffn2, cudaFuncAttributeMaxDynamicSharedMemorySize, SMEM2);

    // prep: x + w3 fp32->fp16 and w1 transpose, one launch
    k_prep<<<PREP_BLKS_TOT, 256>>>(x, w3, w1);

    // fused up+gate+silu (K=D=2048); w2 converted by concurrent warps
    k_ffn1<<<dim3(NT / BM, NH / 128, NE), THREADS1, SMEM1>>>(w2);

    // down-proj (K=H=4096, N=D=2048 in BN=128 tiles, fp32 out)
    k_ffn2<<<dim3(ND / 128, NT / BM, NE), THREADS2, SMEM2>>>(out);
}